// round 13
// baseline (speedup 1.0000x reference)
#include <cuda_runtime.h>

#define LSEQ 256
#define CIN  8
#define COUT 8
#define HID  32
#define XPAD 12     // conv arrays: padded row stride (floats)
#define H1PAD 36    // sh1 row stride
#define W2PAD 36    // sW2 row stride: conflict-free broadcast loads
#define NBLK 256
#define NTHR 256
#define GRP  32     // blocks per o-group

// Scratch: K[o][d][c]
__device__ __align__(16) float g_K[COUT * LSEQ * CIN];
// Per-group barrier state (self-resetting for graph replay)
__device__ volatile unsigned g_bar[COUT] = {0};
__device__ unsigned          g_dep[COUT] = {0};

// ---------------------------------------------------------------------------
// Fused kernel: 256 blocks x 256 threads, 2 CTAs/SM (all 256 co-resident:
// n_conc = 148*2 = 296). Each block: 64 SIREN points + 8 conv positions.
// Phase 1a: thread (pp,q) computes h1[p][4q..4q+3] for points p = pp + 32i.
// Phase 1b: neurons k = q+8m for its 2 points (4 W2 + 2 h loads per j).
// Group barrier: 32 blocks per out-channel, one-thread fence.
// Phase 2: causal conv from smem, 8 warps x 1 position.
// ---------------------------------------------------------------------------
__global__ __launch_bounds__(NTHR, 2) void ckconv_fused(
    const float* __restrict__ x,
    const float* __restrict__ v1, const float* __restrict__ g1,
    const float* __restrict__ b1,
    const float* __restrict__ v2, const float* __restrict__ g2,
    const float* __restrict__ b2,
    const float* __restrict__ w3, const float* __restrict__ b3,
    float* __restrict__ out)
{
    __shared__ float  sW1[HID][3];
    __shared__ float  sb1[HID];
    __shared__ __align__(16) float sW2[HID * W2PAD];
    __shared__ float  sb2[HID];
    __shared__ float  sw3[HID];
    __shared__ float  sb3;
    __shared__ __align__(16) float sh1[64 * H1PAD];
    __shared__ __align__(16) float sk[LSEQ * XPAD];
    __shared__ __align__(16) float sx[LSEQ * XPAD];

    int tid = threadIdx.x;

    // ---------------- phase 0: stage x + weight prep ------------------------
    {
        int r = tid >> 1, hh = (tid & 1) << 2;
        *(float4*)&sx[r * XPAD + hh]         = ((const float4*)x)[tid];
        *(float4*)&sx[(r + 128) * XPAD + hh] = ((const float4*)x)[tid + 256];
    }
    {
        float4 w4 = ((const float4*)v2)[tid];          // 256 float4 = all of v2
        float ss = w4.x * w4.x + w4.y * w4.y + w4.z * w4.z + w4.w * w4.w;
        ss += __shfl_xor_sync(0xFFFFFFFFu, ss, 1);
        ss += __shfl_xor_sync(0xFFFFFFFFu, ss, 2);
        ss += __shfl_xor_sync(0xFFFFFFFFu, ss, 4);
        int row = tid >> 3;
        float inv = g2[row] * rsqrtf(ss);
        float4 nw;
        nw.x = w4.x * inv; nw.y = w4.y * inv; nw.z = w4.z * inv; nw.w = w4.w * inv;
        *(float4*)&sW2[row * W2PAD + ((tid & 7) << 2)] = nw;
    }
    if (tid < HID) {
        float a = v1[tid * 3 + 0];
        float b = v1[tid * 3 + 1];
        float c = v1[tid * 3 + 2];
        float inv1 = g1[tid] * rsqrtf(a * a + b * b + c * c);
        sW1[tid][0] = a * inv1;
        sW1[tid][1] = b * inv1;
        sW1[tid][2] = c * inv1;
        sb1[tid] = b1[tid];
        sb2[tid] = b2[tid];
        sw3[tid] = w3[tid];
        if (tid == 0) sb3 = b3[0];
    }
    __syncthreads();

    // ---------------- coordinates -------------------------------------------
    // Block covers 64 points pid = bid*64 + p; p = d_local*8 + c, d_local<8.
    int pp = tid >> 3;                         // 0..31
    int q  = tid & 7;
    int oc    = blockIdx.x >> 5;               // out channel (block-uniform)
    int tile  = blockIdx.x & 31;               // d-tile / conv i-tile index
    int dtile = tile << 3;                     // 8 d values per block
    float fc = (float)(pp & 7);
    float fo = (float)oc;
    int d0 = dtile + (pp >> 3);                // point i: d = d0 + 4i, i in {0,1}

    // ---------------- phase 1a: h1[p][4q..4q+3] for 2 points ----------------
    {
        float4 hv[2];
        #pragma unroll
        for (int m = 0; m < 4; m++) {
            int h = (q << 2) + m;
            float zb = fmaf(fc, sW1[h][1], fmaf(fo, sW1[h][2], sb1[h]));
            float w0 = sW1[h][0];
            #pragma unroll
            for (int i = 0; i < 2; i++) {
                float dt = -(float)(d0 + (i << 2)) * (1.0f / 256.0f);
                ((float*)&hv[i])[m] = __sinf(fmaf(dt, w0, zb));  // OMEGA = 1
            }
        }
        #pragma unroll
        for (int i = 0; i < 2; i++)
            *(float4*)&sh1[(pp + (i << 5)) * H1PAD + (q << 2)] = hv[i];
    }
    __syncthreads();

    // ---------------- phase 1b: neurons k=q+8m, 2 points ---------------------
    {
        const float* r0 = &sW2[(q     ) * W2PAD];
        const float* r1 = &sW2[(q +  8) * W2PAD];
        const float* r2 = &sW2[(q + 16) * W2PAD];
        const float* r3 = &sW2[(q + 24) * W2PAD];

        float z0[2], z1[2], z2[2], z3[2];
        #pragma unroll
        for (int i = 0; i < 2; i++) {
            z0[i] = sb2[q];
            z1[i] = sb2[q + 8];
            z2[i] = sb2[q + 16];
            z3[i] = sb2[q + 24];
        }

        #pragma unroll
        for (int j = 0; j < 8; j++) {
            float4 h[2];
            #pragma unroll
            for (int i = 0; i < 2; i++)
                h[i] = *(const float4*)&sh1[(pp + (i << 5)) * H1PAD + 4 * j];

            float4 w;
            w = *(const float4*)&r0[4 * j];
            #pragma unroll
            for (int i = 0; i < 2; i++) {
                z0[i] = fmaf(h[i].x, w.x, z0[i]); z0[i] = fmaf(h[i].y, w.y, z0[i]);
                z0[i] = fmaf(h[i].z, w.z, z0[i]); z0[i] = fmaf(h[i].w, w.w, z0[i]);
            }
            w = *(const float4*)&r1[4 * j];
            #pragma unroll
            for (int i = 0; i < 2; i++) {
                z1[i] = fmaf(h[i].x, w.x, z1[i]); z1[i] = fmaf(h[i].y, w.y, z1[i]);
                z1[i] = fmaf(h[i].z, w.z, z1[i]); z1[i] = fmaf(h[i].w, w.w, z1[i]);
            }
            w = *(const float4*)&r2[4 * j];
            #pragma unroll
            for (int i = 0; i < 2; i++) {
                z2[i] = fmaf(h[i].x, w.x, z2[i]); z2[i] = fmaf(h[i].y, w.y, z2[i]);
                z2[i] = fmaf(h[i].z, w.z, z2[i]); z2[i] = fmaf(h[i].w, w.w, z2[i]);
            }
            w = *(const float4*)&r3[4 * j];
            #pragma unroll
            for (int i = 0; i < 2; i++) {
                z3[i] = fmaf(h[i].x, w.x, z3[i]); z3[i] = fmaf(h[i].y, w.y, z3[i]);
                z3[i] = fmaf(h[i].z, w.z, z3[i]); z3[i] = fmaf(h[i].w, w.w, z3[i]);
            }
        }

        float s0 = sw3[q], s1 = sw3[q + 8], s2 = sw3[q + 16], s3 = sw3[q + 24];
        #pragma unroll
        for (int i = 0; i < 2; i++) {
            float acc =        __sinf(z0[i]) * s0;
            acc = fmaf(__sinf(z1[i]), s1, acc);
            acc = fmaf(__sinf(z2[i]), s2, acc);
            acc = fmaf(__sinf(z3[i]), s3, acc);
            acc += __shfl_xor_sync(0xFFFFFFFFu, acc, 1);
            acc += __shfl_xor_sync(0xFFFFFFFFu, acc, 2);
            acc += __shfl_xor_sync(0xFFFFFFFFu, acc, 4);
            if (q == 0)
                g_K[blockIdx.x * 64 + pp + (i << 5)] = acc + sb3;
        }
    }

    // ---------------- group barrier (32 blocks sharing o) -------------------
    int grp = oc;
    __syncthreads();
    if (tid == 0) {
        __threadfence();
        atomicAdd((unsigned*)&g_bar[grp], 1u);
        while (g_bar[grp] < GRP) { }
        __threadfence();
    }
    __syncthreads();

    // ---------------- phase 2: causal conv ----------------------------------
    const float4* k4 = (const float4*)(g_K + oc * (LSEQ * CIN));
    {
        int r = tid >> 1, hh = (tid & 1) << 2;
        float4 a = __ldcg(k4 + tid);
        float4 b = __ldcg(k4 + tid + 256);
        *(float4*)&sk[r * XPAD + hh]         = a;
        *(float4*)&sk[(r + 128) * XPAD + hh] = b;
    }
    __syncthreads();

    {
        int w = tid >> 5, l = tid & 31;        // 8 warps -> 1 position each
        int i = (tile << 3) + w;

        float acc2 = 0.f;
        #pragma unroll
        for (int it = 0; it < 8; it++) {
            if ((it << 5) > i) break;          // warp-uniform early exit
            int dd = l + (it << 5);
            float4 ka = *(const float4*)&sk[dd * XPAD];
            float4 kb = *(const float4*)&sk[dd * XPAD + 4];

            bool v = dd <= i;
            int jc = v ? (i - dd) : 0;
            float m = v ? 1.f : 0.f;

            float4 a0 = *(const float4*)&sx[jc * XPAD];
            float4 b0 = *(const float4*)&sx[jc * XPAD + 4];

            float t = ka.x * a0.x;
            t = fmaf(ka.y, a0.y, t);
            t = fmaf(ka.z, a0.z, t);
            t = fmaf(ka.w, a0.w, t);
            t = fmaf(kb.x, b0.x, t);
            t = fmaf(kb.y, b0.y, t);
            t = fmaf(kb.z, b0.z, t);
            t = fmaf(kb.w, b0.w, t);
            acc2 = fmaf(m, t, acc2);
        }

        #pragma unroll
        for (int s = 16; s > 0; s >>= 1)
            acc2 += __shfl_xor_sync(0xFFFFFFFFu, acc2, s);

        if (l == 0)
            out[i * COUT + oc] = acc2;
    }

    // ---------------- barrier reset (depart counter, replay-safe) -----------
    __syncthreads();
    if (tid == 0) {
        if (atomicAdd(&g_dep[grp], 1u) == GRP - 1u) {
            g_dep[grp] = 0u;
            *(unsigned*)&g_bar[grp] = 0u;
        }
    }
}

// ---------------------------------------------------------------------------
// Launch. Input order: x, t, v1, g1, b1, v2, g2, b2, w3, b3.
// t is the uniform grid arange(L)/L; folded analytically into dt = -d/L.
// ---------------------------------------------------------------------------
extern "C" void kernel_launch(void* const* d_in, const int* in_sizes, int n_in,
                              void* d_out, int out_size)
{
    const float* x  = (const float*)d_in[0];
    const float* v1 = (const float*)d_in[2];
    const float* g1 = (const float*)d_in[3];
    const float* b1 = (const float*)d_in[4];
    const float* v2 = (const float*)d_in[5];
    const float* g2 = (const float*)d_in[6];
    const float* b2 = (const float*)d_in[7];
    const float* w3 = (const float*)d_in[8];
    const float* b3 = (const float*)d_in[9];
    float* out = (float*)d_out;

    ckconv_fused<<<NBLK, NTHR>>>(x, v1, g1, b1, v2, g2, b2, w3, b3, out);
}

// round 14
// speedup vs baseline: 1.4048x; 1.4048x over previous
#include <cuda_runtime.h>

#define LSEQ 256
#define CIN  8
#define COUT 8
#define HID  32
#define XPAD 12     // conv arrays: padded row stride (floats)
#define H1PAD 36    // sh1 row stride
#define W2PAD 36    // sW2 row stride: conflict-free broadcast loads
#define NBLK 128
#define NTHR 512
#define GRP  16     // blocks per o-group

// Scratch: K[o][d][c]
__device__ __align__(16) float g_K[COUT * LSEQ * CIN];
// Per-group barrier state (self-resetting for graph replay)
__device__ volatile unsigned g_bar[COUT] = {0};
__device__ unsigned          g_dep[COUT] = {0};

// ---------------------------------------------------------------------------
// Fused kernel: 128 blocks x 512 threads (single CTA/SM, 16 warps/SM).
// Phase 1a: thread (pg,q) computes h1[p][4q..4q+3] for points p = pg + 64i.
// Phase 1b: neurons k = q+8m for its 2 points; conflict-free broadcast LDS
//           (h: 4 addrs/warp over 16 banks; W2: 8 addrs over all 32 banks).
// Group barrier: 16 blocks per out-channel, one-thread fence.
// Phase 2: causal conv from smem, 16 warps x 1 position.
// ---------------------------------------------------------------------------
__global__ __launch_bounds__(NTHR, 1) void ckconv_fused(
    const float* __restrict__ x,
    const float* __restrict__ v1, const float* __restrict__ g1,
    const float* __restrict__ b1,
    const float* __restrict__ v2, const float* __restrict__ g2,
    const float* __restrict__ b2,
    const float* __restrict__ w3, const float* __restrict__ b3,
    float* __restrict__ out)
{
    __shared__ float  sW1[HID][3];
    __shared__ float  sb1[HID];
    __shared__ __align__(16) float sW2[HID * W2PAD];
    __shared__ float  sb2[HID];
    __shared__ float  sw3[HID];
    __shared__ float  sb3;
    __shared__ __align__(16) float sh1[128 * H1PAD];
    __shared__ __align__(16) float sk[LSEQ * XPAD];
    __shared__ __align__(16) float sx[LSEQ * XPAD];

    int tid = threadIdx.x;

    // ---------------- phase 0: stage x + weight prep ------------------------
    {
        int r = tid >> 1, hh = (tid & 1) << 2;
        *(float4*)&sx[r * XPAD + hh] = ((const float4*)x)[tid];   // 512 f4 = all x
    }
    if (tid < 256) {
        float4 w4 = ((const float4*)v2)[tid];          // 256 float4 = all of v2
        float ss = w4.x * w4.x + w4.y * w4.y + w4.z * w4.z + w4.w * w4.w;
        ss += __shfl_xor_sync(0xFFFFFFFFu, ss, 1);
        ss += __shfl_xor_sync(0xFFFFFFFFu, ss, 2);
        ss += __shfl_xor_sync(0xFFFFFFFFu, ss, 4);
        int row = tid >> 3;
        float inv = g2[row] * rsqrtf(ss);
        float4 nw;
        nw.x = w4.x * inv; nw.y = w4.y * inv; nw.z = w4.z * inv; nw.w = w4.w * inv;
        *(float4*)&sW2[row * W2PAD + ((tid & 7) << 2)] = nw;
    }
    if (tid >= 256 && tid < 256 + HID) {
        int h = tid - 256;
        float a = v1[h * 3 + 0];
        float b = v1[h * 3 + 1];
        float c = v1[h * 3 + 2];
        float inv1 = g1[h] * rsqrtf(a * a + b * b + c * c);
        sW1[h][0] = a * inv1;
        sW1[h][1] = b * inv1;
        sW1[h][2] = c * inv1;
        sb1[h] = b1[h];
        sb2[h] = b2[h];
        sw3[h] = w3[h];
        if (h == 0) sb3 = b3[0];
    }
    __syncthreads();

    // ---------------- coordinates -------------------------------------------
    // Block covers 128 points pid = bid*128 + p, p = pg + 64i (pg<64, i<2).
    // pid = o*2048 + d*8 + c  ->  o = bid>>4 (block-uniform), d = dbase + (p>>3).
    int pg = tid >> 3;                         // 0..63
    int q  = tid & 7;
    int oc    = blockIdx.x >> 4;
    int dbase = (blockIdx.x & 15) << 4;        // 16 d-values / conv i-tile
    float fc = (float)(pg & 7);
    float fo = (float)oc;
    int d0 = dbase + (pg >> 3);                // point i: d = d0 + 8i

    // ---------------- phase 1a: h1[p][4q..4q+3] for 2 points ----------------
    {
        float4 hv[2];
        #pragma unroll
        for (int m = 0; m < 4; m++) {
            int h = (q << 2) + m;
            float zb = fmaf(fc, sW1[h][1], fmaf(fo, sW1[h][2], sb1[h]));
            float w0 = sW1[h][0];
            #pragma unroll
            for (int i = 0; i < 2; i++) {
                float dt = -(float)(d0 + (i << 3)) * (1.0f / 256.0f);
                ((float*)&hv[i])[m] = __sinf(fmaf(dt, w0, zb));  // OMEGA = 1
            }
        }
        #pragma unroll
        for (int i = 0; i < 2; i++)
            *(float4*)&sh1[(pg + (i << 6)) * H1PAD + (q << 2)] = hv[i];
    }
    __syncthreads();

    // ---------------- phase 1b: neurons k=q+8m, 2 points ---------------------
    {
        const float* r0 = &sW2[(q     ) * W2PAD];
        const float* r1 = &sW2[(q +  8) * W2PAD];
        const float* r2 = &sW2[(q + 16) * W2PAD];
        const float* r3 = &sW2[(q + 24) * W2PAD];

        float z0[2], z1[2], z2[2], z3[2];
        #pragma unroll
        for (int i = 0; i < 2; i++) {
            z0[i] = sb2[q];
            z1[i] = sb2[q + 8];
            z2[i] = sb2[q + 16];
            z3[i] = sb2[q + 24];
        }

        #pragma unroll
        for (int j = 0; j < 8; j++) {
            float4 h[2];
            #pragma unroll
            for (int i = 0; i < 2; i++)
                h[i] = *(const float4*)&sh1[(pg + (i << 6)) * H1PAD + 4 * j];

            float4 w;
            w = *(const float4*)&r0[4 * j];
            #pragma unroll
            for (int i = 0; i < 2; i++) {
                z0[i] = fmaf(h[i].x, w.x, z0[i]); z0[i] = fmaf(h[i].y, w.y, z0[i]);
                z0[i] = fmaf(h[i].z, w.z, z0[i]); z0[i] = fmaf(h[i].w, w.w, z0[i]);
            }
            w = *(const float4*)&r1[4 * j];
            #pragma unroll
            for (int i = 0; i < 2; i++) {
                z1[i] = fmaf(h[i].x, w.x, z1[i]); z1[i] = fmaf(h[i].y, w.y, z1[i]);
                z1[i] = fmaf(h[i].z, w.z, z1[i]); z1[i] = fmaf(h[i].w, w.w, z1[i]);
            }
            w = *(const float4*)&r2[4 * j];
            #pragma unroll
            for (int i = 0; i < 2; i++) {
                z2[i] = fmaf(h[i].x, w.x, z2[i]); z2[i] = fmaf(h[i].y, w.y, z2[i]);
                z2[i] = fmaf(h[i].z, w.z, z2[i]); z2[i] = fmaf(h[i].w, w.w, z2[i]);
            }
            w = *(const float4*)&r3[4 * j];
            #pragma unroll
            for (int i = 0; i < 2; i++) {
                z3[i] = fmaf(h[i].x, w.x, z3[i]); z3[i] = fmaf(h[i].y, w.y, z3[i]);
                z3[i] = fmaf(h[i].z, w.z, z3[i]); z3[i] = fmaf(h[i].w, w.w, z3[i]);
            }
        }

        float s0 = sw3[q], s1 = sw3[q + 8], s2 = sw3[q + 16], s3 = sw3[q + 24];
        #pragma unroll
        for (int i = 0; i < 2; i++) {
            float acc =        __sinf(z0[i]) * s0;
            acc = fmaf(__sinf(z1[i]), s1, acc);
            acc = fmaf(__sinf(z2[i]), s2, acc);
            acc = fmaf(__sinf(z3[i]), s3, acc);
            acc += __shfl_xor_sync(0xFFFFFFFFu, acc, 1);
            acc += __shfl_xor_sync(0xFFFFFFFFu, acc, 2);
            acc += __shfl_xor_sync(0xFFFFFFFFu, acc, 4);
            if (q == 0)
                g_K[blockIdx.x * 128 + pg + (i << 6)] = acc + sb3;
        }
    }

    // ---------------- group barrier (16 blocks sharing o) -------------------
    int grp = oc;
    __syncthreads();
    if (tid == 0) {
        __threadfence();
        atomicAdd((unsigned*)&g_bar[grp], 1u);
        while (g_bar[grp] < GRP) { }
        __threadfence();
    }
    __syncthreads();

    // ---------------- phase 2: causal conv ----------------------------------
    const float4* k4 = (const float4*)(g_K + oc * (LSEQ * CIN));
    {
        int r = tid >> 1, hh = (tid & 1) << 2;
        *(float4*)&sk[r * XPAD + hh] = __ldcg(k4 + tid);  // 512 f4 = all K[o]
    }
    __syncthreads();

    {
        int w = tid >> 5, l = tid & 31;        // 16 warps -> 1 position each
        int i = dbase + w;

        float acc2 = 0.f;
        #pragma unroll
        for (int it = 0; it < 8; it++) {
            if ((it << 5) > i) break;          // warp-uniform early exit
            int dd = l + (it << 5);
            float4 ka = *(const float4*)&sk[dd * XPAD];
            float4 kb = *(const float4*)&sk[dd * XPAD + 4];

            bool v = dd <= i;
            int jc = v ? (i - dd) : 0;
            float m = v ? 1.f : 0.f;

            float4 a0 = *(const float4*)&sx[jc * XPAD];
            float4 b0 = *(const float4*)&sx[jc * XPAD + 4];

            float t = ka.x * a0.x;
            t = fmaf(ka.y, a0.y, t);
            t = fmaf(ka.z, a0.z, t);
            t = fmaf(ka.w, a0.w, t);
            t = fmaf(kb.x, b0.x, t);
            t = fmaf(kb.y, b0.y, t);
            t = fmaf(kb.z, b0.z, t);
            t = fmaf(kb.w, b0.w, t);
            acc2 = fmaf(m, t, acc2);
        }

        #pragma unroll
        for (int s = 16; s > 0; s >>= 1)
            acc2 += __shfl_xor_sync(0xFFFFFFFFu, acc2, s);

        if (l == 0)
            out[i * COUT + oc] = acc2;
    }

    // ---------------- barrier reset (depart counter, replay-safe) -----------
    __syncthreads();
    if (tid == 0) {
        if (atomicAdd(&g_dep[grp], 1u) == GRP - 1u) {
            g_dep[grp] = 0u;
            *(unsigned*)&g_bar[grp] = 0u;
        }
    }
}

// ---------------------------------------------------------------------------
// Launch. Input order: x, t, v1, g1, b1, v2, g2, b2, w3, b3.
// t is the uniform grid arange(L)/L; folded analytically into dt = -d/L.
// ---------------------------------------------------------------------------
extern "C" void kernel_launch(void* const* d_in, const int* in_sizes, int n_in,
                              void* d_out, int out_size)
{
    const float* x  = (const float*)d_in[0];
    const float* v1 = (const float*)d_in[2];
    const float* g1 = (const float*)d_in[3];
    const float* b1 = (const float*)d_in[4];
    const float* v2 = (const float*)d_in[5];
    const float* g2 = (const float*)d_in[6];
    const float* b2 = (const float*)d_in[7];
    const float* w3 = (const float*)d_in[8];
    const float* b3 = (const float*)d_in[9];
    float* out = (float*)d_out;

    ckconv_fused<<<NBLK, NTHR>>>(x, v1, g1, b1, v2, g2, b2, w3, b3, out);
}

// round 15
// speedup vs baseline: 1.6857x; 1.2000x over previous
#include <cuda_runtime.h>

#define LSEQ 256
#define CIN  8
#define COUT 8
#define HID  32
#define XPAD 12     // sx row stride (floats): conflict-free LDS.128 at stride 12
#define H1PAD 36    // sh1 row stride
#define W2PAD 36    // sW2 row stride: conflict-free broadcast loads
#define NBLK 128
#define NTHR 256

// ---------------------------------------------------------------------------
// Kernel 0: zero the output (graph replays re-accumulate, so each replay
// starts from zero; idempotent and capture-safe).
// ---------------------------------------------------------------------------
__global__ void zero_out(float* __restrict__ out)
{
    ((float4*)out)[blockIdx.x * 256 + threadIdx.x] = make_float4(0.f, 0.f, 0.f, 0.f);
}

// ---------------------------------------------------------------------------
// Fused kernel, PUSH model: 128 blocks x 256 threads, no inter-block sync.
// Block (o = bid>>4, t = bid&15) evaluates the SIREN kernel-net on its
// 128 points (d in [16t,16t+16), c in [0,8)) -- R12's proven conflict-free
// phases 1a/1b -- keeps K in block smem, then pushes its d-tile's conv
// contributions to out[i = 16t + j, o] via one atomicAdd per thread.
// x-index is j - dd (block-tile independent). No g_K, no barrier, no fence.
// ---------------------------------------------------------------------------
__global__ __launch_bounds__(NTHR, 1) void ckconv_push(
    const float* __restrict__ x,
    const float* __restrict__ v1, const float* __restrict__ g1,
    const float* __restrict__ b1,
    const float* __restrict__ v2, const float* __restrict__ g2,
    const float* __restrict__ b2,
    const float* __restrict__ w3, const float* __restrict__ b3,
    float* __restrict__ out)
{
    __shared__ float  sW1[HID][3];
    __shared__ float  sb1[HID];
    __shared__ __align__(16) float sW2[HID * W2PAD];
    __shared__ float  sb2[HID];
    __shared__ float  sw3[HID];
    __shared__ float  sb3;
    __shared__ __align__(16) float sh1[128 * H1PAD];
    __shared__ __align__(16) float sk[128];        // K[dd][c], dd<16, c<8
    __shared__ __align__(16) float sx[LSEQ * XPAD];

    int tid = threadIdx.x;

    // ---------------- phase 0: stage x + weight prep ------------------------
    {
        int r = tid >> 1, hh = (tid & 1) << 2;
        *(float4*)&sx[r * XPAD + hh]         = ((const float4*)x)[tid];
        *(float4*)&sx[(r + 128) * XPAD + hh] = ((const float4*)x)[tid + 256];
    }
    {
        float4 w4 = ((const float4*)v2)[tid];          // 256 float4 = all of v2
        float ss = w4.x * w4.x + w4.y * w4.y + w4.z * w4.z + w4.w * w4.w;
        ss += __shfl_xor_sync(0xFFFFFFFFu, ss, 1);
        ss += __shfl_xor_sync(0xFFFFFFFFu, ss, 2);
        ss += __shfl_xor_sync(0xFFFFFFFFu, ss, 4);
        int row = tid >> 3;
        float inv = g2[row] * rsqrtf(ss);
        float4 nw;
        nw.x = w4.x * inv; nw.y = w4.y * inv; nw.z = w4.z * inv; nw.w = w4.w * inv;
        *(float4*)&sW2[row * W2PAD + ((tid & 7) << 2)] = nw;
    }
    if (tid < HID) {
        float a = v1[tid * 3 + 0];
        float b = v1[tid * 3 + 1];
        float c = v1[tid * 3 + 2];
        float inv1 = g1[tid] * rsqrtf(a * a + b * b + c * c);
        sW1[tid][0] = a * inv1;
        sW1[tid][1] = b * inv1;
        sW1[tid][2] = c * inv1;
        sb1[tid] = b1[tid];
        sb2[tid] = b2[tid];
        sw3[tid] = w3[tid];
        if (tid == 0) sb3 = b3[0];
    }
    __syncthreads();

    // ---------------- coordinates -------------------------------------------
    // Local point p = pp + 32i  ==  dd*8 + c  (dd = d - dbase < 16, c < 8).
    int pp = tid >> 3;                         // 0..31
    int q  = tid & 7;
    int oc    = blockIdx.x >> 4;               // out channel
    int dbase = (blockIdx.x & 15) << 4;        // d-tile base == i-tile base
    float fc = (float)(pp & 7);
    float fo = (float)oc;
    int d0 = dbase + (pp >> 3);                // point i: d = d0 + 4i

    // ---------------- phase 1a: h1[p][4q..4q+3] for 4 points ----------------
    {
        float4 hv[4];
        #pragma unroll
        for (int m = 0; m < 4; m++) {
            int h = (q << 2) + m;
            float zb = fmaf(fc, sW1[h][1], fmaf(fo, sW1[h][2], sb1[h]));
            float w0 = sW1[h][0];
            #pragma unroll
            for (int i = 0; i < 4; i++) {
                float dt = -(float)(d0 + (i << 2)) * (1.0f / 256.0f);
                ((float*)&hv[i])[m] = __sinf(fmaf(dt, w0, zb));  // OMEGA = 1
            }
        }
        #pragma unroll
        for (int i = 0; i < 4; i++)
            *(float4*)&sh1[(pp + (i << 5)) * H1PAD + (q << 2)] = hv[i];
    }
    __syncthreads();

    // ---------------- phase 1b: neurons k=q+8m, 4 points --------------------
    {
        const float* r0 = &sW2[(q     ) * W2PAD];
        const float* r1 = &sW2[(q +  8) * W2PAD];
        const float* r2 = &sW2[(q + 16) * W2PAD];
        const float* r3 = &sW2[(q + 24) * W2PAD];

        float z0[4], z1[4], z2[4], z3[4];
        #pragma unroll
        for (int i = 0; i < 4; i++) {
            z0[i] = sb2[q];
            z1[i] = sb2[q + 8];
            z2[i] = sb2[q + 16];
            z3[i] = sb2[q + 24];
        }

        #pragma unroll
        for (int j = 0; j < 8; j++) {
            float4 h[4];
            #pragma unroll
            for (int i = 0; i < 4; i++)
                h[i] = *(const float4*)&sh1[(pp + (i << 5)) * H1PAD + 4 * j];

            float4 w;
            w = *(const float4*)&r0[4 * j];
            #pragma unroll
            for (int i = 0; i < 4; i++) {
                z0[i] = fmaf(h[i].x, w.x, z0[i]); z0[i] = fmaf(h[i].y, w.y, z0[i]);
                z0[i] = fmaf(h[i].z, w.z, z0[i]); z0[i] = fmaf(h[i].w, w.w, z0[i]);
            }
            w = *(const float4*)&r1[4 * j];
            #pragma unroll
            for (int i = 0; i < 4; i++) {
                z1[i] = fmaf(h[i].x, w.x, z1[i]); z1[i] = fmaf(h[i].y, w.y, z1[i]);
                z1[i] = fmaf(h[i].z, w.z, z1[i]); z1[i] = fmaf(h[i].w, w.w, z1[i]);
            }
            w = *(const float4*)&r2[4 * j];
            #pragma unroll
            for (int i = 0; i < 4; i++) {
                z2[i] = fmaf(h[i].x, w.x, z2[i]); z2[i] = fmaf(h[i].y, w.y, z2[i]);
                z2[i] = fmaf(h[i].z, w.z, z2[i]); z2[i] = fmaf(h[i].w, w.w, z2[i]);
            }
            w = *(const float4*)&r3[4 * j];
            #pragma unroll
            for (int i = 0; i < 4; i++) {
                z3[i] = fmaf(h[i].x, w.x, z3[i]); z3[i] = fmaf(h[i].y, w.y, z3[i]);
                z3[i] = fmaf(h[i].z, w.z, z3[i]); z3[i] = fmaf(h[i].w, w.w, z3[i]);
            }
        }

        float s0 = sw3[q], s1 = sw3[q + 8], s2 = sw3[q + 16], s3 = sw3[q + 24];
        #pragma unroll
        for (int i = 0; i < 4; i++) {
            float acc =        __sinf(z0[i]) * s0;
            acc = fmaf(__sinf(z1[i]), s1, acc);
            acc = fmaf(__sinf(z2[i]), s2, acc);
            acc = fmaf(__sinf(z3[i]), s3, acc);
            acc += __shfl_xor_sync(0xFFFFFFFFu, acc, 1);
            acc += __shfl_xor_sync(0xFFFFFFFFu, acc, 2);
            acc += __shfl_xor_sync(0xFFFFFFFFu, acc, 4);
            if (q == 0)
                sk[pp + (i << 5)] = acc + sb3;    // == sk[dd*8 + c]
        }
    }
    __syncthreads();

    // ---------------- phase 2: conv push (no inter-block sync) --------------
    // Thread j handles output position i = dbase + j; contributions from
    // this block's d-tile: dd in [0,16), valid when dd <= j. x row = j - dd.
    {
        int j = tid;
        int i = dbase + j;
        if (i < LSEQ) {
            const float4* skv = (const float4*)sk;
            float accv = 0.f;
            #pragma unroll
            for (int dd = 0; dd < 16; dd++) {
                float4 k0 = skv[2 * dd];          // broadcast
                float4 k1 = skv[2 * dd + 1];
                int jr = j - dd;
                bool v = jr >= 0;
                int jx = v ? jr : 0;
                float mm = v ? 1.f : 0.f;
                float4 a0 = *(const float4*)&sx[jx * XPAD];
                float4 b0 = *(const float4*)&sx[jx * XPAD + 4];
                float t = k0.x * a0.x;
                t = fmaf(k0.y, a0.y, t);
                t = fmaf(k0.z, a0.z, t);
                t = fmaf(k0.w, a0.w, t);
                t = fmaf(k1.x, b0.x, t);
                t = fmaf(k1.y, b0.y, t);
                t = fmaf(k1.z, b0.z, t);
                t = fmaf(k1.w, b0.w, t);
                accv = fmaf(mm, t, accv);
            }
            atomicAdd(out + i * COUT + oc, accv);  // fire-and-forget REDG
        }
    }
}

// ---------------------------------------------------------------------------
// Launch: zero out, then push-accumulate. Both graph-capturable.
// Input order: x, t, v1, g1, b1, v2, g2, b2, w3, b3 (t folded analytically).
// ---------------------------------------------------------------------------
extern "C" void kernel_launch(void* const* d_in, const int* in_sizes, int n_in,
                              void* d_out, int out_size)
{
    const float* x  = (const float*)d_in[0];
    const float* v1 = (const float*)d_in[2];
    const float* g1 = (const float*)d_in[3];
    const float* b1 = (const float*)d_in[4];
    const float* v2 = (const float*)d_in[5];
    const float* g2 = (const float*)d_in[6];
    const float* b2 = (const float*)d_in[7];
    const float* w3 = (const float*)d_in[8];
    const float* b3 = (const float*)d_in[9];
    float* out = (float*)d_out;

    zero_out<<<2, 256>>>(out);                  // 2048 floats
    ckconv_push<<<NBLK, NTHR>>>(x, v1, g1, b1, v2, g2, b2, w3, b3, out);
}